// round 4
// baseline (speedup 1.0000x reference)
#include <cuda_runtime.h>
#include <cstdint>

// ---------------- scratch (device globals; no allocs allowed) ----------------
__device__ float  g_hp[8192 * 64];        // h, tf32-rounded, f permuted: [(f%8)*8 + f/8]
__device__ float2 g_e1f1[8192];           // {exp(s1), exp(0.2*s1)}
__device__ float2 g_e2f2[8192];           // {exp(s2), exp(0.2*s2)}
__device__ float  g_part[2 * 8192 * 64];  // partial D per j-half (TRUE f order)
__device__ float  g_lpart[2 * 8192];      // partial softmax denom per j-half

// ---------------- helpers ----------------
__device__ __forceinline__ uint32_t smem_u32(const void* p) {
    uint32_t a;
    asm("{ .reg .u64 t; cvta.to.shared.u64 t, %1; cvt.u32.u64 %0, t; }" : "=r"(a) : "l"(p));
    return a;
}
__device__ __forceinline__ uint32_t tf32_rn(float x) {
    uint32_t u; asm("cvt.rna.tf32.f32 %0, %1;" : "=r"(u) : "f"(x));
    return u;
}
__device__ __forceinline__ void cp_async16(uint32_t saddr, const void* gaddr) {
    asm volatile("cp.async.cg.shared.global [%0], [%1], 16;" :: "r"(saddr), "l"(gaddr) : "memory");
}
#define CP_COMMIT() asm volatile("cp.async.commit_group;" ::: "memory")
#define CP_WAIT(n)  asm volatile("cp.async.wait_group %0;" :: "n"(n) : "memory")

__device__ __forceinline__ void mma_tf32(float* c, uint32_t a0, uint32_t a1, uint32_t a2,
                                         uint32_t a3, uint32_t b0, uint32_t b1) {
    asm volatile(
        "mma.sync.aligned.m16n8k8.row.col.f32.tf32.tf32.f32 "
        "{%0,%1,%2,%3}, {%4,%5,%6,%7}, {%8,%9}, {%0,%1,%2,%3};"
        : "+f"(c[0]), "+f"(c[1]), "+f"(c[2]), "+f"(c[3])
        : "r"(a0), "r"(a1), "r"(a2), "r"(a3), "r"(b0), "r"(b1));
}
__device__ __forceinline__ uint4 lds128(uint32_t addr) {
    uint4 v;
    asm volatile("ld.shared.v4.b32 {%0,%1,%2,%3}, [%4];"
                 : "=r"(v.x), "=r"(v.y), "=r"(v.z), "=r"(v.w) : "r"(addr));
    return v;
}
__device__ __forceinline__ float2 lds64f(uint32_t addr) {
    float2 v;
    asm volatile("ld.shared.v2.f32 {%0,%1}, [%2];" : "=f"(v.x), "=f"(v.y) : "r"(addr));
    return v;
}

// ============================================================================
// K1: h = input@W ; write tf32-rounded f-permuted h, and E1F1/E2F2 factors.
// grid 1024 x 256 threads; each block handles 8 rows.
// ============================================================================
__global__ void __launch_bounds__(256)
gat_prep(const float* __restrict__ inp, const float* __restrict__ W,
         const float* __restrict__ a)
{
    __shared__ float in_s[8][256];
    __shared__ float red[8][4];
    const int tid = threadIdx.x;
    const int base = blockIdx.x * 8;

#pragma unroll
    for (int v = 0; v < 2; v++) {
        const int idx = tid + v * 256;
        const float4 t4 = reinterpret_cast<const float4*>(inp)[(size_t)base * 64 + idx];
        reinterpret_cast<float4*>(&in_s[0][0])[idx] = t4;
    }
    __syncthreads();

    const int f  = tid & 63;   // output feature
    const int rg = tid >> 6;   // row group 0..3 -> rows base+rg and base+rg+4
    float acc0 = 0.f, acc1 = 0.f;
#pragma unroll 8
    for (int k = 0; k < 256; k++) {
        const float w = __ldg(&W[k * 64 + f]);
        acc0 += in_s[rg][k] * w;
        acc1 += in_s[rg + 4][k] * w;
    }
    const int fp = (f & 7) * 8 + (f >> 3);  // permuted feature index
    g_hp[(size_t)(base + rg)     * 64 + fp] = __uint_as_float(tf32_rn(acc0));
    g_hp[(size_t)(base + rg + 4) * 64 + fp] = __uint_as_float(tf32_rn(acc1));

    const float a1 = __ldg(&a[f]);
    const float a2 = __ldg(&a[64 + f]);
    float s10 = acc0 * a1, s20 = acc0 * a2, s11 = acc1 * a1, s21 = acc1 * a2;
#pragma unroll
    for (int o = 16; o > 0; o >>= 1) {
        s10 += __shfl_xor_sync(0xFFFFFFFFu, s10, o);
        s20 += __shfl_xor_sync(0xFFFFFFFFu, s20, o);
        s11 += __shfl_xor_sync(0xFFFFFFFFu, s11, o);
        s21 += __shfl_xor_sync(0xFFFFFFFFu, s21, o);
    }
    const int w = tid >> 5;
    if ((tid & 31) == 0) { red[w][0] = s10; red[w][1] = s20; red[w][2] = s11; red[w][3] = s21; }
    __syncthreads();
    if (tid < 8) {
        const int rr = tid & 3;
        const int hi = tid >> 2;  // 0: acc0 rows, 1: acc1 rows
        const float v1 = red[2 * rr][hi * 2 + 0] + red[2 * rr + 1][hi * 2 + 0];
        const float v2 = red[2 * rr][hi * 2 + 1] + red[2 * rr + 1][hi * 2 + 1];
        const int row = base + rr + hi * 4;
        g_e1f1[row] = make_float2(expf(v1), expf(0.2f * v1));
        g_e2f2[row] = make_float2(expf(v2), expf(0.2f * v2));
    }
}

// ============================================================================
// K2: fused masked attention + (P @ h) via mma.sync tf32 (HMMA).
// grid 128 (64 i-tiles x 2 j-halves), 256 threads (8 warps).
// warp = 16-row strip; full 4096-col j-half per warp.
// P computed directly in A-fragment registers (never touches smem).
// h tiles (128 j-rows x 64 f) double-buffered in smem via cp.async.
// mma #nt with thread-group g supplying packed col g*8+nt covers TRUE
// feature f = nt*8 + (mma-n index); epilogue therefore writes true-f cols.
// ============================================================================
static constexpr int  HSTRIDE   = 68;                       // floats per smem h row (pad)
static constexpr uint32_t SM_E2F2 = 0;                      // 4096 float2 = 32768 B
static constexpr uint32_t SM_H0   = 32768;                  // 128*68*4 = 34816 B
static constexpr uint32_t SM_H1   = SM_H0 + 128 * HSTRIDE * 4;
static constexpr uint32_t SMEM_TOTAL = SM_H1 + 128 * HSTRIDE * 4;  // 102400 B

__global__ void __launch_bounds__(256, 1)
gat_attn(const int* __restrict__ adj)
{
    extern __shared__ char smem[];
    const uint32_t sb = smem_u32(smem);
    const int tid = threadIdx.x;
    const int w   = tid >> 5;
    const int lid = tid & 31;
    const int g   = lid >> 2;   // group id   (fragment row / B n-col)
    const int ctg = lid & 3;    // thread-in-group (k col)
    const int it  = blockIdx.x >> 1;
    const int jh  = blockIdx.x & 1;
    const int ibase = it * 128;
    const int i0 = ibase + w * 16 + g;
    const int i1 = i0 + 8;

    // ---- preload E2F2 for this j-half into smem (2048 float4)
    {
        const float4* src = reinterpret_cast<const float4*>(&g_e2f2[(size_t)jh * 4096]);
        float4* dst = reinterpret_cast<float4*>(smem + SM_E2F2);
#pragma unroll
        for (int v = 0; v < 8; v++) dst[tid + v * 256] = src[tid + v * 256];
    }

    // ---- preload h tile 0 via cp.async (8 x 16B per thread)
    {
        const float* src = &g_hp[(size_t)jh * 4096 * 64];
#pragma unroll
        for (int v = 0; v < 8; v++) {
            const int id = tid + v * 256;          // 0..2047 float4s
            const int r  = id >> 4, c4 = id & 15;
            cp_async16(sb + SM_H0 + (r * HSTRIDE + c4 * 4) * 4, src + r * 64 + c4 * 4);
        }
        CP_COMMIT();
    }

    const float2 ef0 = g_e1f1[i0];
    const float2 ef1 = g_e1f1[i1];
    const int* __restrict__ ar0 = adj + (size_t)i0 * 8192 + jh * 4096;
    const int* __restrict__ ar1 = adj + (size_t)i1 * 8192 + jh * 4096;

    float C[8][4];
#pragma unroll
    for (int n = 0; n < 8; n++)
#pragma unroll
        for (int q = 0; q < 4; q++) C[n][q] = 0.f;
    float lacc0 = 0.f, lacc1 = 0.f;

    for (int t = 0; t < 32; t++) {
        const uint32_t hb = (t & 1) ? SM_H1 : SM_H0;

        if (t < 31) {  // prefetch next tile into other buffer
            const uint32_t hn = (t & 1) ? SM_H0 : SM_H1;
            const float* src = &g_hp[((size_t)jh * 4096 + (t + 1) * 128) * 64];
#pragma unroll
            for (int v = 0; v < 8; v++) {
                const int id = tid + v * 256;
                const int r  = id >> 4, c4 = id & 15;
                cp_async16(sb + hn + (r * HSTRIDE + c4 * 4) * 4, src + r * 64 + c4 * 4);
            }
            CP_COMMIT();
            CP_WAIT(1);
        } else {
            CP_WAIT(0);
        }
        __syncthreads();

#pragma unroll 4
        for (int kk = 0; kk < 16; kk++) {
            const int lj = kk * 8;               // local j within tile
            const int jj = t * 128 + lj;         // j within half

            // masks
            const int m00 = ar0[jj + ctg];
            const int m01 = ar0[jj + ctg + 4];
            const int m10 = ar1[jj + ctg];
            const int m11 = ar1[jj + ctg + 4];

            // column factors
            const float2 c0 = lds64f(sb + SM_E2F2 + (jj + ctg) * 8);
            const float2 c1 = lds64f(sb + SM_E2F2 + (jj + ctg + 4) * 8);

            // P = adj ? max(E1*E2, F1*F2) : 0   (== exp(leaky(s1+s2)) masked)
            float p00 = m00 ? fmaxf(ef0.x * c0.x, ef0.y * c0.y) : 0.f;
            float p10 = m10 ? fmaxf(ef1.x * c0.x, ef1.y * c0.y) : 0.f;
            float p01 = m01 ? fmaxf(ef0.x * c1.x, ef0.y * c1.y) : 0.f;
            float p11 = m11 ? fmaxf(ef1.x * c1.x, ef1.y * c1.y) : 0.f;

            const uint32_t a0 = tf32_rn(p00), a1r = tf32_rn(p10);
            const uint32_t a2 = tf32_rn(p01), a3 = tf32_rn(p11);
            lacc0 += __uint_as_float(a0) + __uint_as_float(a2);
            lacc1 += __uint_as_float(a1r) + __uint_as_float(a3);

            // B fragments: rows lj+ctg and lj+ctg+4, packed cols g*8 .. g*8+7
            const uint32_t rb0 = sb + hb + ((lj + ctg) * HSTRIDE + g * 8) * 4;
            const uint32_t rb1 = sb + hb + ((lj + ctg + 4) * HSTRIDE + g * 8) * 4;
            const uint4 bl0 = lds128(rb0);
            const uint4 bl1 = lds128(rb0 + 16);
            const uint4 bh0 = lds128(rb1);
            const uint4 bh1 = lds128(rb1 + 16);

            mma_tf32(C[0], a0, a1r, a2, a3, bl0.x, bh0.x);
            mma_tf32(C[1], a0, a1r, a2, a3, bl0.y, bh0.y);
            mma_tf32(C[2], a0, a1r, a2, a3, bl0.z, bh0.z);
            mma_tf32(C[3], a0, a1r, a2, a3, bl0.w, bh0.w);
            mma_tf32(C[4], a0, a1r, a2, a3, bl1.x, bh1.x);
            mma_tf32(C[5], a0, a1r, a2, a3, bl1.y, bh1.y);
            mma_tf32(C[6], a0, a1r, a2, a3, bl1.z, bh1.z);
            mma_tf32(C[7], a0, a1r, a2, a3, bl1.w, bh1.w);
        }
        __syncthreads();
    }

    // ---- row-sum reduction across the 4 threads of the group
    lacc0 += __shfl_xor_sync(0xFFFFFFFFu, lacc0, 1);
    lacc0 += __shfl_xor_sync(0xFFFFFFFFu, lacc0, 2);
    lacc1 += __shfl_xor_sync(0xFFFFFFFFu, lacc1, 1);
    lacc1 += __shfl_xor_sync(0xFFFFFFFFu, lacc1, 2);
    if (ctg == 0) {
        g_lpart[(size_t)jh * 8192 + i0] = lacc0;
        g_lpart[(size_t)jh * 8192 + i1] = lacc1;
    }

    // ---- write D partials. mma #nt covers TRUE f = nt*8 + (mma-n).
    // c0/c1 -> mma-n = 2*ctg, 2*ctg+1 at row g; c2/c3 same cols at row g+8.
    float* d0 = &g_part[((size_t)jh * 8192 + i0) * 64];
    float* d1 = &g_part[((size_t)jh * 8192 + i1) * 64];
#pragma unroll
    for (int nt = 0; nt < 8; nt++) {
        const int col = nt * 8 + 2 * ctg;
        *reinterpret_cast<float2*>(&d0[col]) = make_float2(C[nt][0], C[nt][1]);
        *reinterpret_cast<float2*>(&d1[col]) = make_float2(C[nt][2], C[nt][3]);
    }
}

// ============================================================================
// K3: combine partials, normalize, elu. g_part is already in TRUE f order
// (the permutation was consumed by the mma wiring) -> direct float4 out.
// ============================================================================
__device__ __forceinline__ float eluf(float x) { return x > 0.f ? x : expm1f(x); }

__global__ void __launch_bounds__(256)
gat_final(float* __restrict__ out)
{
    const int gi = blockIdx.x * 256 + threadIdx.x;  // 0..131071
    const int i  = gi >> 4;
    const int c0 = (gi & 15) * 4;
    const float4 d0 = *reinterpret_cast<const float4*>(&g_part[(size_t)i * 64 + c0]);
    const float4 d1 = *reinterpret_cast<const float4*>(&g_part[(size_t)(8192 + i) * 64 + c0]);
    const float inv = 1.0f / (g_lpart[i] + g_lpart[8192 + i]);
    float4 o;
    o.x = eluf((d0.x + d1.x) * inv);
    o.y = eluf((d0.y + d1.y) * inv);
    o.z = eluf((d0.z + d1.z) * inv);
    o.w = eluf((d0.w + d1.w) * inv);
    *reinterpret_cast<float4*>(&out[(size_t)i * 64 + c0]) = o;
}

// ============================================================================
extern "C" void kernel_launch(void* const* d_in, const int* in_sizes, int n_in,
                              void* d_out, int out_size)
{
    const float* inp = (const float*)d_in[0];
    const int*   adj = (const int*)d_in[1];
    const float* W   = (const float*)d_in[2];
    const float* a   = (const float*)d_in[3];
    float* out = (float*)d_out;

    cudaFuncSetAttribute((const void*)gat_attn,
                         cudaFuncAttributeMaxDynamicSharedMemorySize, SMEM_TOTAL);

    gat_prep<<<1024, 256>>>(inp, W, a);
    gat_attn<<<128, 256, SMEM_TOTAL>>>(adj);
    gat_final<<<512, 256>>>(out);
}

// round 5
// speedup vs baseline: 1.2936x; 1.2936x over previous
#include <cuda_runtime.h>
#include <cstdint>

// ---------------- scratch (device globals; no allocs allowed) ----------------
__device__ float    g_hp[8192 * 64];        // h, tf32-rounded, f permuted: [(f%8)*8 + f/8]
__device__ float2   g_e1f1[8192];           // {exp(s1), exp(0.2*s1)}
__device__ float2   g_e2f2[8192];           // {exp(s2), exp(0.2*s2)}
__device__ uint32_t g_madj[8192 * 256];     // packed adj bits: [(i*64+q)*4+c] bit l = adj[i][q*128+4l+c]
__device__ float    g_part[2 * 8192 * 64];  // partial D per j-half (TRUE f order)
__device__ float    g_lpart[2 * 8192];      // partial softmax denom per j-half

// ---------------- helpers ----------------
__device__ __forceinline__ uint32_t smem_u32(const void* p) {
    uint32_t a;
    asm("{ .reg .u64 t; cvta.to.shared.u64 t, %1; cvt.u32.u64 %0, t; }" : "=r"(a) : "l"(p));
    return a;
}
__device__ __forceinline__ uint32_t tf32_rn(float x) {
    uint32_t u; asm("cvt.rna.tf32.f32 %0, %1;" : "=r"(u) : "f"(x));
    return u;
}
__device__ __forceinline__ void cp_async16(uint32_t saddr, const void* gaddr) {
    asm volatile("cp.async.cg.shared.global [%0], [%1], 16;" :: "r"(saddr), "l"(gaddr) : "memory");
}
#define CP_COMMIT() asm volatile("cp.async.commit_group;" ::: "memory")
#define CP_WAIT(n)  asm volatile("cp.async.wait_group %0;" :: "n"(n) : "memory")

__device__ __forceinline__ void mma_tf32(float* c, uint32_t a0, uint32_t a1, uint32_t a2,
                                         uint32_t a3, uint32_t b0, uint32_t b1) {
    asm volatile(
        "mma.sync.aligned.m16n8k8.row.col.f32.tf32.tf32.f32 "
        "{%0,%1,%2,%3}, {%4,%5,%6,%7}, {%8,%9}, {%0,%1,%2,%3};"
        : "+f"(c[0]), "+f"(c[1]), "+f"(c[2]), "+f"(c[3])
        : "r"(a0), "r"(a1), "r"(a2), "r"(a3), "r"(b0), "r"(b1));
}
__device__ __forceinline__ uint4 lds128(uint32_t addr) {
    uint4 v;
    asm volatile("ld.shared.v4.b32 {%0,%1,%2,%3}, [%4];"
                 : "=r"(v.x), "=r"(v.y), "=r"(v.z), "=r"(v.w) : "r"(addr));
    return v;
}
__device__ __forceinline__ float2 lds64f(uint32_t addr) {
    float2 v;
    asm volatile("ld.shared.v2.f32 {%0,%1}, [%2];" : "=f"(v.x), "=f"(v.y) : "r"(addr));
    return v;
}

// ============================================================================
// K0: pack adj into bitmasks. grid 4096 x 256 (8 warps); warp = (row, q-quarter).
// Perfectly coalesced 512B reads per warp-iteration; ballot assembles bits.
// ============================================================================
__global__ void __launch_bounds__(256)
gat_pack(const int* __restrict__ adj)
{
    const int wg   = blockIdx.x * 8 + (threadIdx.x >> 5);  // 0..32767
    const int lane = threadIdx.x & 31;
    const int i    = wg >> 2;
    const int q0   = (wg & 3) * 16;
    const int4* src = reinterpret_cast<const int4*>(adj) + (size_t)i * 2048;
#pragma unroll 4
    for (int q = q0; q < q0 + 16; q++) {
        const int4 m = src[q * 32 + lane];
        const uint32_t b0 = __ballot_sync(0xFFFFFFFFu, m.x != 0);
        const uint32_t b1 = __ballot_sync(0xFFFFFFFFu, m.y != 0);
        const uint32_t b2 = __ballot_sync(0xFFFFFFFFu, m.z != 0);
        const uint32_t b3 = __ballot_sync(0xFFFFFFFFu, m.w != 0);
        if (lane == 0)
            *reinterpret_cast<uint4*>(&g_madj[((size_t)i * 64 + q) * 4]) =
                make_uint4(b0, b1, b2, b3);
    }
}

// ============================================================================
// K1: h = input@W (W staged in smem); write tf32-rounded f-permuted h and
// E1F1/E2F2 factors. grid 1024 x 256; block handles 8 rows.
// dynamic smem: W 64KB + in_s 8KB.
// ============================================================================
static constexpr uint32_t PREP_SMEM = 64 * 1024 + 8 * 1024;

__global__ void __launch_bounds__(256)
gat_prep(const float* __restrict__ inp, const float* __restrict__ W,
         const float* __restrict__ a)
{
    extern __shared__ float dsm[];
    float* W_s  = dsm;          // 16384 floats
    float* in_s = dsm + 16384;  // 8*256 floats
    __shared__ float red[8][4];
    const int tid = threadIdx.x;
    const int base = blockIdx.x * 8;

    // stage W (4096 float4)
#pragma unroll
    for (int v = 0; v < 16; v++)
        reinterpret_cast<float4*>(W_s)[tid + v * 256] =
            reinterpret_cast<const float4*>(W)[tid + v * 256];
    // stage input rows (512 float4)
#pragma unroll
    for (int v = 0; v < 2; v++) {
        const int idx = tid + v * 256;
        reinterpret_cast<float4*>(in_s)[idx] =
            reinterpret_cast<const float4*>(inp)[(size_t)base * 64 + idx];
    }
    __syncthreads();

    const int f  = tid & 63;   // output feature
    const int rg = tid >> 6;   // row group 0..3 -> rows base+rg and base+rg+4
    const float* inr0 = in_s + rg * 256;
    const float* inr1 = in_s + (rg + 4) * 256;
    float acc0 = 0.f, acc1 = 0.f;
#pragma unroll 16
    for (int k = 0; k < 256; k++) {
        const float w = W_s[k * 64 + f];
        acc0 += inr0[k] * w;
        acc1 += inr1[k] * w;
    }
    const int fp = (f & 7) * 8 + (f >> 3);  // permuted feature index
    g_hp[(size_t)(base + rg)     * 64 + fp] = __uint_as_float(tf32_rn(acc0));
    g_hp[(size_t)(base + rg + 4) * 64 + fp] = __uint_as_float(tf32_rn(acc1));

    const float a1 = __ldg(&a[f]);
    const float a2 = __ldg(&a[64 + f]);
    float s10 = acc0 * a1, s20 = acc0 * a2, s11 = acc1 * a1, s21 = acc1 * a2;
#pragma unroll
    for (int o = 16; o > 0; o >>= 1) {
        s10 += __shfl_xor_sync(0xFFFFFFFFu, s10, o);
        s20 += __shfl_xor_sync(0xFFFFFFFFu, s20, o);
        s11 += __shfl_xor_sync(0xFFFFFFFFu, s11, o);
        s21 += __shfl_xor_sync(0xFFFFFFFFu, s21, o);
    }
    const int w = tid >> 5;
    if ((tid & 31) == 0) { red[w][0] = s10; red[w][1] = s20; red[w][2] = s11; red[w][3] = s21; }
    __syncthreads();
    if (tid < 8) {
        const int rr = tid & 3;
        const int hi = tid >> 2;  // 0: acc0 rows, 1: acc1 rows
        const float v1 = red[2 * rr][hi * 2 + 0] + red[2 * rr + 1][hi * 2 + 0];
        const float v2 = red[2 * rr][hi * 2 + 1] + red[2 * rr + 1][hi * 2 + 1];
        const int row = base + rr + hi * 4;
        g_e1f1[row] = make_float2(expf(v1), expf(0.2f * v1));
        g_e2f2[row] = make_float2(expf(v2), expf(0.2f * v2));
    }
}

// ============================================================================
// K2: fused masked attention + (P @ h) via mma.sync tf32 (HMMA).
// grid 128 (64 i-tiles x 2 j-halves), 256 threads (8 warps).
// Masks come from packed bits: one uint32 per row per 128-j tile per thread.
// P computed directly in A-fragment registers; h double-buffered via cp.async.
// mma #nt covers TRUE feature f = nt*8 + (mma n-index).
// ============================================================================
static constexpr int  HSTRIDE   = 68;                       // floats per smem h row (pad)
static constexpr uint32_t SM_E2F2 = 0;                      // 4096 float2 = 32768 B
static constexpr uint32_t SM_H0   = 32768;                  // 128*68*4 = 34816 B
static constexpr uint32_t SM_H1   = SM_H0 + 128 * HSTRIDE * 4;
static constexpr uint32_t SMEM_TOTAL = SM_H1 + 128 * HSTRIDE * 4;  // 102400 B

__global__ void __launch_bounds__(256, 1)
gat_attn()
{
    extern __shared__ char smem[];
    const uint32_t sb = smem_u32(smem);
    const int tid = threadIdx.x;
    const int w   = tid >> 5;
    const int lid = tid & 31;
    const int g   = lid >> 2;   // group id (fragment row / B n-col)
    const int ctg = lid & 3;    // thread-in-group (k col)
    const int it  = blockIdx.x >> 1;
    const int jh  = blockIdx.x & 1;
    const int ibase = it * 128;
    const int i0 = ibase + w * 16 + g;
    const int i1 = i0 + 8;

    // ---- preload E2F2 for this j-half into smem (2048 float4)
    {
        const float4* src = reinterpret_cast<const float4*>(&g_e2f2[(size_t)jh * 4096]);
        float4* dst = reinterpret_cast<float4*>(smem + SM_E2F2);
#pragma unroll
        for (int v = 0; v < 8; v++) dst[tid + v * 256] = src[tid + v * 256];
    }

    // ---- preload h tile 0 via cp.async (8 x 16B per thread)
    {
        const float* src = &g_hp[(size_t)jh * 4096 * 64];
#pragma unroll
        for (int v = 0; v < 8; v++) {
            const int id = tid + v * 256;          // 0..2047 float4s
            const int r  = id >> 4, c4 = id & 15;
            cp_async16(sb + SM_H0 + (r * HSTRIDE + c4 * 4) * 4, src + r * 64 + c4 * 4);
        }
        CP_COMMIT();
    }

    const float2 ef0 = g_e1f1[i0];
    const float2 ef1 = g_e1f1[i1];
    const uint32_t* __restrict__ mrow0 = &g_madj[((size_t)i0 * 64 + jh * 32) * 4 + ctg];
    const uint32_t* __restrict__ mrow1 = &g_madj[((size_t)i1 * 64 + jh * 32) * 4 + ctg];

    float C[8][4];
#pragma unroll
    for (int n = 0; n < 8; n++)
#pragma unroll
        for (int q = 0; q < 4; q++) C[n][q] = 0.f;
    float lacc0 = 0.f, lacc1 = 0.f;

    uint32_t wm0 = mrow0[0];
    uint32_t wm1 = mrow1[0];

    for (int t = 0; t < 32; t++) {
        const uint32_t hb = (t & 1) ? SM_H1 : SM_H0;

        if (t < 31) {  // prefetch next h tile into other buffer
            const uint32_t hn = (t & 1) ? SM_H0 : SM_H1;
            const float* src = &g_hp[((size_t)jh * 4096 + (t + 1) * 128) * 64];
#pragma unroll
            for (int v = 0; v < 8; v++) {
                const int id = tid + v * 256;
                const int r  = id >> 4, c4 = id & 15;
                cp_async16(sb + hn + (r * HSTRIDE + c4 * 4) * 4, src + r * 64 + c4 * 4);
            }
            CP_COMMIT();
            CP_WAIT(1);
        } else {
            CP_WAIT(0);
        }
        __syncthreads();

        uint32_t r0 = wm0, r1 = wm1;
        if (t < 31) {  // prefetch next tile's mask words (L2-resident)
            wm0 = mrow0[(t + 1) * 4];
            wm1 = mrow1[(t + 1) * 4];
        }

#pragma unroll 4
        for (int kk = 0; kk < 16; kk++) {
            const int lj = kk * 8;               // local j within tile
            const int jj = t * 128 + lj;         // j within half

            // column factors (broadcast LDS: addr depends only on ctg)
            const float2 c0 = lds64f(sb + SM_E2F2 + (jj + ctg) * 8);
            const float2 c1 = lds64f(sb + SM_E2F2 + (jj + ctg + 4) * 8);

            // P = adj ? max(E1*E2, F1*F2) : 0   (== exp(leaky(s1+s2)) masked)
            float p00 = (r0 & 1u) ? fmaxf(ef0.x * c0.x, ef0.y * c0.y) : 0.f;
            float p01 = (r0 & 2u) ? fmaxf(ef0.x * c1.x, ef0.y * c1.y) : 0.f;
            float p10 = (r1 & 1u) ? fmaxf(ef1.x * c0.x, ef1.y * c0.y) : 0.f;
            float p11 = (r1 & 2u) ? fmaxf(ef1.x * c1.x, ef1.y * c1.y) : 0.f;
            r0 >>= 2; r1 >>= 2;

            const uint32_t a0 = tf32_rn(p00), a1r = tf32_rn(p10);
            const uint32_t a2 = tf32_rn(p01), a3 = tf32_rn(p11);
            lacc0 += __uint_as_float(a0) + __uint_as_float(a2);
            lacc1 += __uint_as_float(a1r) + __uint_as_float(a3);

            // B fragments: rows lj+ctg and lj+ctg+4, packed cols g*8 .. g*8+7
            const uint32_t rb0 = sb + hb + ((lj + ctg) * HSTRIDE + g * 8) * 4;
            const uint32_t rb1 = sb + hb + ((lj + ctg + 4) * HSTRIDE + g * 8) * 4;
            const uint4 bl0 = lds128(rb0);
            const uint4 bl1 = lds128(rb0 + 16);
            const uint4 bh0 = lds128(rb1);
            const uint4 bh1 = lds128(rb1 + 16);

            mma_tf32(C[0], a0, a1r, a2, a3, bl0.x, bh0.x);
            mma_tf32(C[1], a0, a1r, a2, a3, bl0.y, bh0.y);
            mma_tf32(C[2], a0, a1r, a2, a3, bl0.z, bh0.z);
            mma_tf32(C[3], a0, a1r, a2, a3, bl0.w, bh0.w);
            mma_tf32(C[4], a0, a1r, a2, a3, bl1.x, bh1.x);
            mma_tf32(C[5], a0, a1r, a2, a3, bl1.y, bh1.y);
            mma_tf32(C[6], a0, a1r, a2, a3, bl1.z, bh1.z);
            mma_tf32(C[7], a0, a1r, a2, a3, bl1.w, bh1.w);
        }
        __syncthreads();
    }

    // ---- row-sum reduction across the 4 threads of the group
    lacc0 += __shfl_xor_sync(0xFFFFFFFFu, lacc0, 1);
    lacc0 += __shfl_xor_sync(0xFFFFFFFFu, lacc0, 2);
    lacc1 += __shfl_xor_sync(0xFFFFFFFFu, lacc1, 1);
    lacc1 += __shfl_xor_sync(0xFFFFFFFFu, lacc1, 2);
    if (ctg == 0) {
        g_lpart[(size_t)jh * 8192 + i0] = lacc0;
        g_lpart[(size_t)jh * 8192 + i1] = lacc1;
    }

    // ---- write D partials (TRUE f order): mma #nt covers f = nt*8 + mma-n
    float* d0 = &g_part[((size_t)jh * 8192 + i0) * 64];
    float* d1 = &g_part[((size_t)jh * 8192 + i1) * 64];
#pragma unroll
    for (int nt = 0; nt < 8; nt++) {
        const int col = nt * 8 + 2 * ctg;
        *reinterpret_cast<float2*>(&d0[col]) = make_float2(C[nt][0], C[nt][1]);
        *reinterpret_cast<float2*>(&d1[col]) = make_float2(C[nt][2], C[nt][3]);
    }
}

// ============================================================================
// K3: combine partials, normalize, elu. g_part is already in TRUE f order.
// ============================================================================
__device__ __forceinline__ float eluf(float x) { return x > 0.f ? x : expm1f(x); }

__global__ void __launch_bounds__(256)
gat_final(float* __restrict__ out)
{
    const int gi = blockIdx.x * 256 + threadIdx.x;  // 0..131071
    const int i  = gi >> 4;
    const int c0 = (gi & 15) * 4;
    const float4 d0 = *reinterpret_cast<const float4*>(&g_part[(size_t)i * 64 + c0]);
    const float4 d1 = *reinterpret_cast<const float4*>(&g_part[(size_t)(8192 + i) * 64 + c0]);
    const float inv = 1.0f / (g_lpart[i] + g_lpart[8192 + i]);
    float4 o;
    o.x = eluf((d0.x + d1.x) * inv);
    o.y = eluf((d0.y + d1.y) * inv);
    o.z = eluf((d0.z + d1.z) * inv);
    o.w = eluf((d0.w + d1.w) * inv);
    *reinterpret_cast<float4*>(&out[(size_t)i * 64 + c0]) = o;
}

// ============================================================================
extern "C" void kernel_launch(void* const* d_in, const int* in_sizes, int n_in,
                              void* d_out, int out_size)
{
    const float* inp = (const float*)d_in[0];
    const int*   adj = (const int*)d_in[1];
    const float* W   = (const float*)d_in[2];
    const float* a   = (const float*)d_in[3];
    float* out = (float*)d_out;

    cudaFuncSetAttribute((const void*)gat_prep,
                         cudaFuncAttributeMaxDynamicSharedMemorySize, PREP_SMEM);
    cudaFuncSetAttribute((const void*)gat_attn,
                         cudaFuncAttributeMaxDynamicSharedMemorySize, SMEM_TOTAL);

    gat_pack<<<4096, 256>>>(adj);
    gat_prep<<<1024, 256, PREP_SMEM>>>(inp, W, a);
    gat_attn<<<128, 256, SMEM_TOTAL>>>();
    gat_final<<<512, 256>>>(out);
}

// round 6
// speedup vs baseline: 1.7027x; 1.3162x over previous
#include <cuda_runtime.h>
#include <cstdint>

// ---------------- scratch (device globals; no allocs allowed) ----------------
__device__ float    g_hp[8192 * 64];        // h, tf32-rounded, f permuted: [(f%8)*8 + f/8]
__device__ float2   g_e1f1[8192];           // {exp(s1), exp(0.2*s1)}
__device__ float2   g_e2f2[8192];           // {exp(s2), exp(0.2*s2)}
__device__ float    g_part[8 * 8192 * 64];  // partial D per j-chunk (TRUE f order)
__device__ float    g_lpart[8 * 8192];      // partial softmax denom per j-chunk

// ---------------- helpers ----------------
__device__ __forceinline__ uint32_t smem_u32(const void* p) {
    uint32_t a;
    asm("{ .reg .u64 t; cvta.to.shared.u64 t, %1; cvt.u32.u64 %0, t; }" : "=r"(a) : "l"(p));
    return a;
}
__device__ __forceinline__ uint32_t tf32_rn(float x) {
    uint32_t u; asm("cvt.rna.tf32.f32 %0, %1;" : "=r"(u) : "f"(x));
    return u;
}
__device__ __forceinline__ void cp_async16(uint32_t saddr, const void* gaddr) {
    asm volatile("cp.async.cg.shared.global [%0], [%1], 16;" :: "r"(saddr), "l"(gaddr) : "memory");
}
#define CP_COMMIT() asm volatile("cp.async.commit_group;" ::: "memory")
#define CP_WAIT(n)  asm volatile("cp.async.wait_group %0;" :: "n"(n) : "memory")

__device__ __forceinline__ void mma_tf32(float* c, uint32_t a0, uint32_t a1, uint32_t a2,
                                         uint32_t a3, uint32_t b0, uint32_t b1) {
    asm volatile(
        "mma.sync.aligned.m16n8k8.row.col.f32.tf32.tf32.f32 "
        "{%0,%1,%2,%3}, {%4,%5,%6,%7}, {%8,%9}, {%0,%1,%2,%3};"
        : "+f"(c[0]), "+f"(c[1]), "+f"(c[2]), "+f"(c[3])
        : "r"(a0), "r"(a1), "r"(a2), "r"(a3), "r"(b0), "r"(b1));
}
__device__ __forceinline__ uint4 lds128(uint32_t addr) {
    uint4 v;
    asm volatile("ld.shared.v4.b32 {%0,%1,%2,%3}, [%4];"
                 : "=r"(v.x), "=r"(v.y), "=r"(v.z), "=r"(v.w) : "r"(addr));
    return v;
}
__device__ __forceinline__ float2 lds64f(uint32_t addr) {
    float2 v;
    asm volatile("ld.shared.v2.f32 {%0,%1}, [%2];" : "=f"(v.x), "=f"(v.y) : "r"(addr));
    return v;
}
__device__ __forceinline__ uint32_t lds32(uint32_t addr) {
    uint32_t v;
    asm volatile("ld.shared.b32 %0, [%1];" : "=r"(v) : "r"(addr));
    return v;
}

// ============================================================================
// K1: h = input@W (W staged in smem); write tf32-rounded f-permuted h and
// E1F1/E2F2 factors. grid 1024 x 256; block handles 8 rows.
// ============================================================================
static constexpr uint32_t PREP_SMEM = 64 * 1024 + 8 * 1024;

__global__ void __launch_bounds__(256)
gat_prep(const float* __restrict__ inp, const float* __restrict__ W,
         const float* __restrict__ a)
{
    extern __shared__ float dsm[];
    float* W_s  = dsm;          // 16384 floats
    float* in_s = dsm + 16384;  // 8*256 floats
    __shared__ float red[8][4];
    const int tid = threadIdx.x;
    const int base = blockIdx.x * 8;

#pragma unroll
    for (int v = 0; v < 16; v++)
        reinterpret_cast<float4*>(W_s)[tid + v * 256] =
            reinterpret_cast<const float4*>(W)[tid + v * 256];
#pragma unroll
    for (int v = 0; v < 2; v++) {
        const int idx = tid + v * 256;
        reinterpret_cast<float4*>(in_s)[idx] =
            reinterpret_cast<const float4*>(inp)[(size_t)base * 64 + idx];
    }
    __syncthreads();

    const int f  = tid & 63;
    const int rg = tid >> 6;
    const float* inr0 = in_s + rg * 256;
    const float* inr1 = in_s + (rg + 4) * 256;
    float acc0 = 0.f, acc1 = 0.f;
#pragma unroll 16
    for (int k = 0; k < 256; k++) {
        const float w = W_s[k * 64 + f];
        acc0 += inr0[k] * w;
        acc1 += inr1[k] * w;
    }
    const int fp = (f & 7) * 8 + (f >> 3);  // permuted feature index
    g_hp[(size_t)(base + rg)     * 64 + fp] = __uint_as_float(tf32_rn(acc0));
    g_hp[(size_t)(base + rg + 4) * 64 + fp] = __uint_as_float(tf32_rn(acc1));

    const float a1 = __ldg(&a[f]);
    const float a2 = __ldg(&a[64 + f]);
    float s10 = acc0 * a1, s20 = acc0 * a2, s11 = acc1 * a1, s21 = acc1 * a2;
#pragma unroll
    for (int o = 16; o > 0; o >>= 1) {
        s10 += __shfl_xor_sync(0xFFFFFFFFu, s10, o);
        s20 += __shfl_xor_sync(0xFFFFFFFFu, s20, o);
        s11 += __shfl_xor_sync(0xFFFFFFFFu, s11, o);
        s21 += __shfl_xor_sync(0xFFFFFFFFu, s21, o);
    }
    const int w = tid >> 5;
    if ((tid & 31) == 0) { red[w][0] = s10; red[w][1] = s20; red[w][2] = s11; red[w][3] = s21; }
    __syncthreads();
    if (tid < 8) {
        const int rr = tid & 3;
        const int hi = tid >> 2;
        const float v1 = red[2 * rr][hi * 2 + 0] + red[2 * rr + 1][hi * 2 + 0];
        const float v2 = red[2 * rr][hi * 2 + 1] + red[2 * rr + 1][hi * 2 + 1];
        const int row = base + rr + hi * 4;
        g_e1f1[row] = make_float2(expf(v1), expf(0.2f * v1));
        g_e2f2[row] = make_float2(expf(v2), expf(0.2f * v2));
    }
}

// ============================================================================
// K2: fused adj-pack + masked attention + (P @ h) via mma.sync tf32.
// grid 256 = 32 i-tiles (256 rows) x 8 j-chunks (1024 cols); 256 thr, 2 CTA/SM.
// warp = 32 rows (two m16 A-fragments sharing each B-fragment).
// adj converted to bitmasks in-kernel (LDG.128 + ballot -> smem, dbl-buffered).
// l computed by an extra MMA against B = 1.0 (bias-cancelling with D).
// ============================================================================
static constexpr int  HSTRIDE   = 68;                       // floats per smem h row
static constexpr uint32_t SM_E2F2 = 0;                      // 1024 float2 = 8192 B
static constexpr uint32_t SM_MASK = 8192;                   // 2 x 4096 B (256 rows x uint4)
static constexpr uint32_t SM_H0   = 16384;                  // 128*68*4 = 34816 B
static constexpr uint32_t SM_H1   = SM_H0 + 128 * HSTRIDE * 4;
static constexpr uint32_t SMEM_TOTAL = SM_H1 + 128 * HSTRIDE * 4;  // 86016 B
static constexpr uint32_t ONE_TF32 = 0x3f800000u;           // 1.0f (exact tf32)

__global__ void __launch_bounds__(256, 2)
gat_attn(const int* __restrict__ adj)
{
    extern __shared__ char smem[];
    const uint32_t sb = smem_u32(smem);
    const int tid = threadIdx.x;
    const int w   = tid >> 5;
    const int lane = tid & 31;
    const int g   = lane >> 2;  // fragment row within block
    const int ctg = lane & 3;   // k col
    const int it  = blockIdx.x >> 3;
    const int jq  = blockIdx.x & 7;
    const int ibase = it * 256;
    const int jbase = jq * 1024;
    const int rbase = ibase + w * 32;      // this warp's 32 rows

    // ---- preload E2F2 slice (1024 entries = 512 float4)
    {
        const float4* src = reinterpret_cast<const float4*>(&g_e2f2[jbase]);
        float4* dst = reinterpret_cast<float4*>(smem + SM_E2F2);
        dst[tid]       = src[tid];
        dst[tid + 256] = src[tid + 256];
    }

    // ---- preload h tile 0 via cp.async (8 x 16B per thread)
    {
        const float* src = &g_hp[(size_t)jbase * 64];
#pragma unroll
        for (int v = 0; v < 8; v++) {
            const int id = tid + v * 256;          // 0..2047 float4s
            const int r  = id >> 4, c4 = id & 15;
            cp_async16(sb + SM_H0 + (r * HSTRIDE + c4 * 4) * 4, src + r * 64 + c4 * 4);
        }
        CP_COMMIT();
    }

    // ---- convert masks for tile 0 (warp-private smem region)
    {
        const int* src = adj + (size_t)rbase * 8192 + jbase;
        const uint32_t mb = sb + SM_MASK + (uint32_t)(w * 32) * 16u;
#pragma unroll 4
        for (int r = 0; r < 32; r++) {
            const int4 m = reinterpret_cast<const int4*>(src + (size_t)r * 8192)[lane];
            const uint32_t b0 = __ballot_sync(0xFFFFFFFFu, m.x != 0);
            const uint32_t b1 = __ballot_sync(0xFFFFFFFFu, m.y != 0);
            const uint32_t b2 = __ballot_sync(0xFFFFFFFFu, m.z != 0);
            const uint32_t b3 = __ballot_sync(0xFFFFFFFFu, m.w != 0);
            if (lane == 0)
                asm volatile("st.shared.v4.b32 [%0], {%1,%2,%3,%4};"
                             :: "r"(mb + r * 16), "r"(b0), "r"(b1), "r"(b2), "r"(b3)
                             : "memory");
        }
        __syncwarp();
    }

    const float2 ef0 = g_e1f1[rbase + g];
    const float2 ef1 = g_e1f1[rbase + g + 8];
    const float2 ef2 = g_e1f1[rbase + g + 16];
    const float2 ef3 = g_e1f1[rbase + g + 24];

    float C0[8][4], C1[8][4], S0[4], S1[4];
#pragma unroll
    for (int n = 0; n < 8; n++)
#pragma unroll
        for (int q = 0; q < 4; q++) { C0[n][q] = 0.f; C1[n][q] = 0.f; }
#pragma unroll
    for (int q = 0; q < 4; q++) { S0[q] = 0.f; S1[q] = 0.f; }

    for (int t = 0; t < 8; t++) {
        const uint32_t hb = (t & 1) ? SM_H1 : SM_H0;

        if (t < 7) {  // prefetch next h tile into other buffer
            const uint32_t hn = (t & 1) ? SM_H0 : SM_H1;
            const float* src = &g_hp[((size_t)jbase + (t + 1) * 128) * 64];
#pragma unroll
            for (int v = 0; v < 8; v++) {
                const int id = tid + v * 256;
                const int r  = id >> 4, c4 = id & 15;
                cp_async16(sb + hn + (r * HSTRIDE + c4 * 4) * 4, src + r * 64 + c4 * 4);
            }
            CP_COMMIT();
            CP_WAIT(1);
        } else {
            CP_WAIT(0);
        }
        __syncthreads();

        // fetch this warp's 4 mask words for tile t
        const uint32_t mbR = sb + SM_MASK + ((t & 1) ? 4096u : 0u)
                           + (uint32_t)(w * 32) * 16u + (uint32_t)ctg * 4u;
        uint32_t r0 = lds32(mbR + (g +  0) * 16);
        uint32_t r1 = lds32(mbR + (g +  8) * 16);
        uint32_t r2 = lds32(mbR + (g + 16) * 16);
        uint32_t r3 = lds32(mbR + (g + 24) * 16);

#pragma unroll 2
        for (int kk = 0; kk < 16; kk++) {
            const int lj = kk * 8;               // local j within tile
            const int jj = t * 128 + lj;         // j within chunk

            // column factors (broadcast LDS)
            const float2 c0 = lds64f(sb + SM_E2F2 + (jj + ctg) * 8);
            const float2 c1 = lds64f(sb + SM_E2F2 + (jj + ctg + 4) * 8);

            // P = adj ? max(E1*E2, F1*F2) : 0   (== exp(leaky(s1+s2)) masked)
            const float pL0 = (r0 & 1u) ? fmaxf(ef0.x * c0.x, ef0.y * c0.y) : 0.f;
            const float pH0 = (r0 & 2u) ? fmaxf(ef0.x * c1.x, ef0.y * c1.y) : 0.f;
            const float pL1 = (r1 & 1u) ? fmaxf(ef1.x * c0.x, ef1.y * c0.y) : 0.f;
            const float pH1 = (r1 & 2u) ? fmaxf(ef1.x * c1.x, ef1.y * c1.y) : 0.f;
            const float pL2 = (r2 & 1u) ? fmaxf(ef2.x * c0.x, ef2.y * c0.y) : 0.f;
            const float pH2 = (r2 & 2u) ? fmaxf(ef2.x * c1.x, ef2.y * c1.y) : 0.f;
            const float pL3 = (r3 & 1u) ? fmaxf(ef3.x * c0.x, ef3.y * c0.y) : 0.f;
            const float pH3 = (r3 & 2u) ? fmaxf(ef3.x * c1.x, ef3.y * c1.y) : 0.f;
            r0 >>= 2; r1 >>= 2; r2 >>= 2; r3 >>= 2;

            // A fragments (HW truncation bias cancels in D/l ratio)
            const uint32_t a00 = __float_as_uint(pL0), a01 = __float_as_uint(pL1);
            const uint32_t a02 = __float_as_uint(pH0), a03 = __float_as_uint(pH1);
            const uint32_t a10 = __float_as_uint(pL2), a11 = __float_as_uint(pL3);
            const uint32_t a12 = __float_as_uint(pH2), a13 = __float_as_uint(pH3);

            // B fragments: rows lj+ctg and lj+ctg+4, packed cols g*8 .. g*8+7
            const uint32_t rb0 = sb + hb + ((lj + ctg) * HSTRIDE + g * 8) * 4;
            const uint32_t rb1 = sb + hb + ((lj + ctg + 4) * HSTRIDE + g * 8) * 4;
            const uint4 bl0 = lds128(rb0);
            const uint4 bl1 = lds128(rb0 + 16);
            const uint4 bh0 = lds128(rb1);
            const uint4 bh1 = lds128(rb1 + 16);

            mma_tf32(C0[0], a00, a01, a02, a03, bl0.x, bh0.x);
            mma_tf32(C1[0], a10, a11, a12, a13, bl0.x, bh0.x);
            mma_tf32(C0[1], a00, a01, a02, a03, bl0.y, bh0.y);
            mma_tf32(C1[1], a10, a11, a12, a13, bl0.y, bh0.y);
            mma_tf32(C0[2], a00, a01, a02, a03, bl0.z, bh0.z);
            mma_tf32(C1[2], a10, a11, a12, a13, bl0.z, bh0.z);
            mma_tf32(C0[3], a00, a01, a02, a03, bl0.w, bh0.w);
            mma_tf32(C1[3], a10, a11, a12, a13, bl0.w, bh0.w);
            mma_tf32(C0[4], a00, a01, a02, a03, bl1.x, bh1.x);
            mma_tf32(C1[4], a10, a11, a12, a13, bl1.x, bh1.x);
            mma_tf32(C0[5], a00, a01, a02, a03, bl1.y, bh1.y);
            mma_tf32(C1[5], a10, a11, a12, a13, bl1.y, bh1.y);
            mma_tf32(C0[6], a00, a01, a02, a03, bl1.z, bh1.z);
            mma_tf32(C1[6], a10, a11, a12, a13, bl1.z, bh1.z);
            mma_tf32(C0[7], a00, a01, a02, a03, bl1.w, bh1.w);
            mma_tf32(C1[7], a10, a11, a12, a13, bl1.w, bh1.w);
            // row sums (l) via ones-column MMA
            mma_tf32(S0, a00, a01, a02, a03, ONE_TF32, ONE_TF32);
            mma_tf32(S1, a10, a11, a12, a13, ONE_TF32, ONE_TF32);
        }

        if (t < 7) {  // convert masks for tile t+1 (warp-private; overlaps tail)
            const int* src = adj + (size_t)rbase * 8192 + jbase + (t + 1) * 128;
            const uint32_t mb = sb + SM_MASK + ((t & 1) ? 0u : 4096u)
                              + (uint32_t)(w * 32) * 16u;
#pragma unroll 4
            for (int r = 0; r < 32; r++) {
                const int4 m = reinterpret_cast<const int4*>(src + (size_t)r * 8192)[lane];
                const uint32_t b0 = __ballot_sync(0xFFFFFFFFu, m.x != 0);
                const uint32_t b1 = __ballot_sync(0xFFFFFFFFu, m.y != 0);
                const uint32_t b2 = __ballot_sync(0xFFFFFFFFu, m.z != 0);
                const uint32_t b3 = __ballot_sync(0xFFFFFFFFu, m.w != 0);
                if (lane == 0)
                    asm volatile("st.shared.v4.b32 [%0], {%1,%2,%3,%4};"
                                 :: "r"(mb + r * 16), "r"(b0), "r"(b1), "r"(b2), "r"(b3)
                                 : "memory");
            }
            __syncwarp();
        }
        __syncthreads();
    }

    // ---- l write (S values identical across the 4 threads of each group)
    if (ctg == 0) {
        float* lp = &g_lpart[(size_t)jq * 8192];
        lp[rbase + g]      = S0[0];
        lp[rbase + g + 8]  = S0[2];
        lp[rbase + g + 16] = S1[0];
        lp[rbase + g + 24] = S1[2];
    }

    // ---- write D partials (TRUE f order): mma #nt covers f = nt*8 + mma-n
    float* d0 = &g_part[((size_t)jq * 8192 + rbase + g) * 64];
    float* d1 = d0 + 8 * 64;
    float* d2 = d0 + 16 * 64;
    float* d3 = d0 + 24 * 64;
#pragma unroll
    for (int nt = 0; nt < 8; nt++) {
        const int col = nt * 8 + 2 * ctg;
        *reinterpret_cast<float2*>(&d0[col]) = make_float2(C0[nt][0], C0[nt][1]);
        *reinterpret_cast<float2*>(&d1[col]) = make_float2(C0[nt][2], C0[nt][3]);
        *reinterpret_cast<float2*>(&d2[col]) = make_float2(C1[nt][0], C1[nt][1]);
        *reinterpret_cast<float2*>(&d3[col]) = make_float2(C1[nt][2], C1[nt][3]);
    }
}

// ============================================================================
// K3: combine 8 partials, normalize, elu. g_part is in TRUE f order.
// ============================================================================
__device__ __forceinline__ float eluf(float x) { return x > 0.f ? x : expm1f(x); }

__global__ void __launch_bounds__(256)
gat_final(float* __restrict__ out)
{
    const int gi = blockIdx.x * 256 + threadIdx.x;  // 0..131071
    const int i  = gi >> 4;
    const int c0 = (gi & 15) * 4;
    float4 acc = *reinterpret_cast<const float4*>(&g_part[(size_t)i * 64 + c0]);
    float l = g_lpart[i];
#pragma unroll
    for (int q = 1; q < 8; q++) {
        const float4 d = *reinterpret_cast<const float4*>(
            &g_part[((size_t)q * 8192 + i) * 64 + c0]);
        acc.x += d.x; acc.y += d.y; acc.z += d.z; acc.w += d.w;
        l += g_lpart[(size_t)q * 8192 + i];
    }
    const float inv = 1.0f / l;
    float4 o;
    o.x = eluf(acc.x * inv);
    o.y = eluf(acc.y * inv);
    o.z = eluf(acc.z * inv);
    o.w = eluf(acc.w * inv);
    *reinterpret_cast<float4*>(&out[(size_t)i * 64 + c0]) = o;
}

// ============================================================================
extern "C" void kernel_launch(void* const* d_in, const int* in_sizes, int n_in,
                              void* d_out, int out_size)
{
    const float* inp = (const float*)d_in[0];
    const int*   adj = (const int*)d_in[1];
    const float* W   = (const float*)d_in[2];
    const float* a   = (const float*)d_in[3];
    float* out = (float*)d_out;

    cudaFuncSetAttribute((const void*)gat_prep,
                         cudaFuncAttributeMaxDynamicSharedMemorySize, PREP_SMEM);
    cudaFuncSetAttribute((const void*)gat_attn,
                         cudaFuncAttributeMaxDynamicSharedMemorySize, SMEM_TOTAL);

    gat_prep<<<1024, 256, PREP_SMEM>>>(inp, W, a);
    gat_attn<<<256, 256, SMEM_TOTAL>>>(adj);
    gat_final<<<512, 256>>>(out);
}